// round 13
// baseline (speedup 1.0000x reference)
#include <cuda_runtime.h>
#include <math.h>

#define NN 20000
#define NE 50000
#define HH 128
#define UCNT 256
#define MAXDEG 512
#define DSCALE 0.17677669529663687f   // 1/sqrt(32)
#define NTHR 256
#define SMEM_SZ 167936                // 2x64KB weights + 4KB rows + 32KB partials
#define SEH ((size_t)UCNT * MAXDEG * HH)

// ---------------- device scratch (static, no allocation) ----------------
__device__ int   g_n2s[NN];          // slot+1; 0 = none
__device__ unsigned char g_nneed[NN];
__device__ int   g_deg[UCNT];
__device__ int   g_eidx[UCNT * MAXDEG];
__device__ int   g_nbr[UCNT * MAXDEG];
__device__ int   g_Lcnt;
__device__ int   g_Llist[NN], g_nodeL[NN];
__device__ int   g_tgtL[UCNT], g_canon[UCNT], g_hasnbr[UCNT];
__device__ int   g_rowSlot[NN];      // slot+1; 0 = none

__device__ int   g_poff[UCNT + 1];
__device__ int   g_Ptot;
__device__ int   g_pSlot[UCNT * MAXDEG];
__device__ float g_pT[UCNT * MAXDEG];
__device__ int   g_pNbrRow[UCNT * MAXDEG];

__device__ float g_xL[NN * HH];
__device__ float g_tfL[NN * HH];
__device__ float g_q[UCNT * HH];
__device__ float g_agg[UCNT * HH];
__device__ float g_sTE[2 * SEH];     // per-layer time-encoder pair vectors
__device__ float g_V[SEH];
__device__ float g_sc[UCNT * MAXDEG * 4];

#define WT_TOTAL 294912
__device__ float g_Wt[WT_TOTAL];

__constant__ int c_moutD[19] = {128,128,128,128,128,128,128,128,128,
                                128,128,128,128,128,128,128, 64,128, 64};
__constant__ int c_moff[19]  = {0,16384,32768,49152,65536,81920,98304,114688,
                                131072,147456,163840,180224,196608,212992,
                                229376,245760,262144,270336,286720};

// ---------------- device-wide barrier ----------------
__device__ unsigned g_cnt8[8];
__device__ unsigned g_rootc;
__device__ volatile unsigned g_ep;

__device__ __forceinline__ void gridsync() {
    __syncthreads();
    if (threadIdx.x == 0) {
        unsigned nb = gridDim.x;
        unsigned e = g_ep;
        __threadfence();
        unsigned g = blockIdx.x & 7u;
        unsigned sz = nb / 8u + ((g < (nb & 7u)) ? 1u : 0u);
        if (atomicAdd(&g_cnt8[g], 1u) == sz - 1u) {
            g_cnt8[g] = 0u;
            __threadfence();
            if (atomicAdd(&g_rootc, 1u) == 7u) {
                g_rootc = 0u;
                __threadfence();
                g_ep = e + 1u;
            }
        }
        while (g_ep == e) { }
        __threadfence();
    }
    __syncthreads();
}

// ---------------- helpers ----------------
__device__ __forceinline__ float4 relu4(float4 v) {
    v.x = fmaxf(v.x, 0.f); v.y = fmaxf(v.y, 0.f);
    v.z = fmaxf(v.z, 0.f); v.w = fmaxf(v.w, 0.f);
    return v;
}

__device__ __forceinline__ float matvec64(const float* __restrict__ v,
                                          const float* __restrict__ Wt,
                                          int d, int stride) {
    float a0 = 0.f, a1 = 0.f, a2 = 0.f, a3 = 0.f;
#pragma unroll 8
    for (int k = 0; k < 64; k += 4) {
        a0 = fmaf(v[k],     Wt[(k)     * stride + d], a0);
        a1 = fmaf(v[k + 1], Wt[(k + 1) * stride + d], a1);
        a2 = fmaf(v[k + 2], Wt[(k + 2) * stride + d], a2);
        a3 = fmaf(v[k + 3], Wt[(k + 3) * stride + d], a3);
    }
    return (a0 + a1) + (a2 + a3);
}

__device__ __forceinline__ float matvec(const float* __restrict__ v,
                                        const float* __restrict__ Wt,
                                        int d, int stride, int K) {
    float a0 = 0.f, a1 = 0.f, a2 = 0.f, a3 = 0.f;
#pragma unroll 8
    for (int k = 0; k < K; k += 4) {
        a0 = fmaf(v[k],     Wt[(k)     * stride + d], a0);
        a1 = fmaf(v[k + 1], Wt[(k + 1) * stride + d], a1);
        a2 = fmaf(v[k + 2], Wt[(k + 2) * stride + d], a2);
        a3 = fmaf(v[k + 3], Wt[(k + 3) * stride + d], a3);
    }
    return (a0 + a1) + (a2 + a3);
}

// ---------------- 8-row k-split GEMM stage (smem weights) -------------------
// gsel: 0 linear, 1 Llist, 2 tgtL, 3 relu(rowSlot? aggAux : in), 4 time-encode
struct GJob {
    const float* in; const float* pA; const float* pB; const float* bias;
    float* out;
    int gsel, woff, cnt;
};

__device__ void gemm_stage(float* sm, GJob jb) {
    float* s_w = sm;                                        // 16384 floats (64KB)
    float (*s_in)[HH] = (float(*)[HH])(sm + 16384);         // 8 x 128
    float4 (*s_part)[8][32] = (float4(*)[8][32])(sm + 16384 + 8 * HH);
    int tid = threadIdx.x, w = tid >> 5, lane = tid & 31;
    int k4 = lane * 4;
    int cnt = jb.cnt;
    int T = (cnt + 7) >> 3;
    const float4* wp = (const float4*)(g_Wt + jb.woff);
    bool loaded = false;

    for (int t = blockIdx.x; t < T; t += gridDim.x) {
        if (!loaded) {
            for (int i = tid; i < 4096; i += NTHR)
                ((float4*)s_w)[i] = wp[i];
            loaded = true;
        }
        int r0 = t * 8;
        {
            int r = r0 + w;
            int rc = (r < cnt) ? r : (cnt - 1);
            float4 v;
            if (jb.gsel == 0) {
                v = *(const float4*)(jb.in + (size_t)rc * HH + k4);
            } else if (jb.gsel == 1) {
                v = *(const float4*)(jb.in + (size_t)g_Llist[rc] * HH + k4);
            } else if (jb.gsel == 2) {
                v = *(const float4*)(jb.in + (size_t)g_tgtL[rc] * HH + k4);
            } else if (jb.gsel == 3) {
                int s = g_rowSlot[rc];
                const float* src = (s > 0) ? (jb.pA + (size_t)(s - 1) * HH)
                                           : (jb.in + (size_t)rc * HH);
                v = relu4(*(const float4*)(src + k4));
            } else {  // 4: time-encode stage 1
                float tv = g_pT[rc];
                float4 w1 = *(const float4*)(jb.pA + k4);
                float4 b1 = *(const float4*)(jb.pB + k4);
                v.x = fmaxf(fmaf(tv, w1.x, b1.x), 0.f);
                v.y = fmaxf(fmaf(tv, w1.y, b1.y), 0.f);
                v.z = fmaxf(fmaf(tv, w1.z, b1.z), 0.f);
                v.w = fmaxf(fmaf(tv, w1.w, b1.w), 0.f);
            }
            *(float4*)(&s_in[w][k4]) = v;
        }
        __syncthreads();

        float4 acc[8];
#pragma unroll
        for (int r = 0; r < 8; r++) acc[r] = make_float4(0.f, 0.f, 0.f, 0.f);
        int kbase = w * 16;
#pragma unroll
        for (int kk = 0; kk < 16; kk++) {
            int k = kbase + kk;
            float4 wv = ((const float4*)s_w)[k * 32 + lane];
#pragma unroll
            for (int r = 0; r < 8; r++) {
                float xv = s_in[r][k];
                acc[r].x = fmaf(xv, wv.x, acc[r].x);
                acc[r].y = fmaf(xv, wv.y, acc[r].y);
                acc[r].z = fmaf(xv, wv.z, acc[r].z);
                acc[r].w = fmaf(xv, wv.w, acc[r].w);
            }
        }
#pragma unroll
        for (int r = 0; r < 8; r++) s_part[w][r][lane] = acc[r];
        __syncthreads();

        {
            float4 o = s_part[0][w][lane];
#pragma unroll
            for (int ww = 1; ww < 8; ww++) {
                float4 p = s_part[ww][w][lane];
                o.x += p.x; o.y += p.y; o.z += p.z; o.w += p.w;
            }
            float4 bv = jb.bias ? ((const float4*)jb.bias)[lane]
                                : make_float4(0.f, 0.f, 0.f, 0.f);
            int row = r0 + w;
            if (row < cnt) {
                o.x += bv.x; o.y += bv.y; o.z += bv.z; o.w += bv.w;
                *(float4*)(jb.out + (size_t)row * HH + k4) = o;
            }
        }
        __syncthreads();
    }
}

// ---------------- fused K-score + V stage (both weights in smem) ------------
// row = g_sTE[l][rc] + g_tfL[pNbrRow[rc]]  (combined s formed on the fly)
__device__ void kv_stage(float* sm, const float* __restrict__ sTE,
                         int wkoff, int wvoff,
                         const float* __restrict__ bk,
                         const float* __restrict__ bvv, int cnt) {
    float* s_wk = sm;
    float* s_wv = sm + 16384;
    float (*s_in)[HH] = (float(*)[HH])(sm + 32768);
    float4 (*s_part)[8][32] = (float4(*)[8][32])(sm + 32768 + 8 * HH);
    int tid = threadIdx.x, w = tid >> 5, lane = tid & 31;
    int k4 = lane * 4;
    int T = (cnt + 7) >> 3;
    const float4* wkp = (const float4*)(g_Wt + wkoff);
    const float4* wvp = (const float4*)(g_Wt + wvoff);
    bool loaded = false;

    for (int t = blockIdx.x; t < T; t += gridDim.x) {
        if (!loaded) {
            for (int i = tid; i < 4096; i += NTHR) {
                ((float4*)s_wk)[i] = wkp[i];
                ((float4*)s_wv)[i] = wvp[i];
            }
            loaded = true;
        }
        int r0 = t * 8;
        {
            int r = r0 + w;
            int rc = (r < cnt) ? r : (cnt - 1);
            float4 a = *(const float4*)(sTE + (size_t)rc * HH + k4);
            int nr = g_pNbrRow[rc];
            float4 b = *(const float4*)(g_tfL + (size_t)nr * HH + k4);
            a.x += b.x; a.y += b.y; a.z += b.z; a.w += b.w;
            *(float4*)(&s_in[w][k4]) = a;
        }
        __syncthreads();

        int kbase = w * 16;
        // ---- K + score epilogue ----
        {
            float4 acc[8];
#pragma unroll
            for (int r = 0; r < 8; r++) acc[r] = make_float4(0.f, 0.f, 0.f, 0.f);
#pragma unroll
            for (int kk = 0; kk < 16; kk++) {
                int k = kbase + kk;
                float4 wv = ((const float4*)s_wk)[k * 32 + lane];
#pragma unroll
                for (int r = 0; r < 8; r++) {
                    float xv = s_in[r][k];
                    acc[r].x = fmaf(xv, wv.x, acc[r].x);
                    acc[r].y = fmaf(xv, wv.y, acc[r].y);
                    acc[r].z = fmaf(xv, wv.z, acc[r].z);
                    acc[r].w = fmaf(xv, wv.w, acc[r].w);
                }
            }
#pragma unroll
            for (int r = 0; r < 8; r++) s_part[w][r][lane] = acc[r];
        }
        __syncthreads();
        {
            float4 o = s_part[0][w][lane];
#pragma unroll
            for (int ww = 1; ww < 8; ww++) {
                float4 p = s_part[ww][w][lane];
                o.x += p.x; o.y += p.y; o.z += p.z; o.w += p.w;
            }
            float4 bv = ((const float4*)bk)[lane];
            int row = r0 + w;
            int rowc = (row < cnt) ? row : (cnt - 1);
            int u = g_pSlot[rowc];
            float4 q4 = *(const float4*)(g_q + (size_t)u * HH + k4);
            float p = (o.x + bv.x) * q4.x + (o.y + bv.y) * q4.y
                    + (o.z + bv.z) * q4.z + (o.w + bv.w) * q4.w;
            p += __shfl_xor_sync(0xffffffffu, p, 4);
            p += __shfl_xor_sync(0xffffffffu, p, 2);
            p += __shfl_xor_sync(0xffffffffu, p, 1);
            if ((lane & 7) == 0 && row < cnt)
                g_sc[rowc * 4 + (lane >> 3)] = p * DSCALE;
        }
        __syncthreads();
        // ---- V ----
        {
            float4 acc[8];
#pragma unroll
            for (int r = 0; r < 8; r++) acc[r] = make_float4(0.f, 0.f, 0.f, 0.f);
#pragma unroll
            for (int kk = 0; kk < 16; kk++) {
                int k = kbase + kk;
                float4 wv = ((const float4*)s_wv)[k * 32 + lane];
#pragma unroll
                for (int r = 0; r < 8; r++) {
                    float xv = s_in[r][k];
                    acc[r].x = fmaf(xv, wv.x, acc[r].x);
                    acc[r].y = fmaf(xv, wv.y, acc[r].y);
                    acc[r].z = fmaf(xv, wv.z, acc[r].z);
                    acc[r].w = fmaf(xv, wv.w, acc[r].w);
                }
            }
#pragma unroll
            for (int r = 0; r < 8; r++) s_part[w][r][lane] = acc[r];
        }
        __syncthreads();
        {
            float4 o = s_part[0][w][lane];
#pragma unroll
            for (int ww = 1; ww < 8; ww++) {
                float4 p = s_part[ww][w][lane];
                o.x += p.x; o.y += p.y; o.z += p.z; o.w += p.w;
            }
            float4 bv = ((const float4*)bvv)[lane];
            int row = r0 + w;
            if (row < cnt) {
                o.x += bv.x; o.y += bv.y; o.z += bv.z; o.w += bv.w;
                *(float4*)(g_V + (size_t)row * HH + k4) = o;
            }
        }
        __syncthreads();
    }
}

// ---------------- fin body for one slot: result -> dst (smem or global) -----
__device__ void fin_one(float* sm, int u,
                        const float* __restrict__ Waot, const float* __restrict__ aoB,
                        const float* __restrict__ Wopt, const float* __restrict__ opB,
                        float* __restrict__ dst, int applyRelu) {
    float* sSc  = sm;                  // MAXDEG*4
    float* sO   = sm + MAXDEG * 4;     // 128
    float* sTgt = sO + 128;            // 128
    float* sTmp = sTgt + 128;          // 128
    float (*sPart)[128] = (float(*)[128])(sTmp + 128);   // 2 x 128
    int tid = threadIdx.x;
    int half = tid >> 7;
    int dd = tid & 127;
    int hh2 = dd >> 5;

    int off = g_poff[u];
    int dg = g_poff[u + 1] - off;
    for (int i = tid; i < dg * 4; i += NTHR) sSc[i] = g_sc[off * 4 + i];
    if (tid < 128) sTgt[dd] = g_tfL[(size_t)g_tgtL[u] * HH + dd];
    __syncthreads();

    if (tid < 128) {
        int lane = tid & 31, hh = tid >> 5;
        float mx = -1e30f;
        for (int j = lane; j < dg; j += 32) mx = fmaxf(mx, sSc[j * 4 + hh]);
#pragma unroll
        for (int m = 16; m > 0; m >>= 1)
            mx = fmaxf(mx, __shfl_xor_sync(0xffffffffu, mx, m));
        float smv = 0.f;
        for (int j = lane; j < dg; j += 32) {
            float p = expf(sSc[j * 4 + hh] - mx);
            sSc[j * 4 + hh] = p;
            smv += p;
        }
#pragma unroll
        for (int m = 16; m > 0; m >>= 1)
            smv += __shfl_xor_sync(0xffffffffu, smv, m);
        float inv = (dg > 0) ? (1.f / smv) : 0.f;
        for (int j = lane; j < dg; j += 32) sSc[j * 4 + hh] *= inv;
    }
    __syncthreads();

    {
        float p = 0.f;
        for (int j = half; j < dg; j += 2)
            p = fmaf(sSc[j * 4 + hh2], g_V[((size_t)(off + j)) * HH + dd], p);
        sPart[half][dd] = p;
    }
    __syncthreads();
    if (tid < 128) sO[dd] = sPart[0][dd] + sPart[1][dd];
    __syncthreads();

    sPart[half][dd] = matvec64(sO + half * 64, Waot + half * 64 * HH, dd, HH);
    __syncthreads();
    if (tid < 128)
        sTmp[dd] = (dg > 0) ? (sPart[0][dd] + sPart[1][dd] + aoB[dd]) : sTgt[dd];
    __syncthreads();

    sPart[half][dd] = matvec64(sTmp + half * 64, Wopt + half * 64 * HH, dd, HH);
    __syncthreads();
    if (tid < 128) {
        float v = sPart[0][dd] + sPart[1][dd] + opB[dd];
        dst[dd] = applyRelu ? fmaxf(v, 0.f) : v;
    }
    __syncthreads();
}

// ---------------- mega kernel ----------------
struct Params {
    const float* wsrc[19];
    const int *tp, *src, *dst;
    const float *ets, *nf;
    const float *in_b, *teW1, *teB1, *teB2, *aiB, *aoB, *ftB, *opB;
    const float *o1B, *o2B, *l1B, *l2B, *l3W, *l3B;
};

__global__ void __launch_bounds__(NTHR)
k_mega(Params P, float* out) {
    extern __shared__ float sm[];
    const int gt = blockIdx.x * NTHR + threadIdx.x;
    const int gs = gridDim.x * NTHR;
    int tid = threadIdx.x;

    // ---- S0: weight transpose + mark targets ----
    for (int m = 0; m < 19; m++) {
        int outD = c_moutD[m];
        int tot = outD * 128;
        const float* s = P.wsrc[m];
        float* dst = g_Wt + c_moff[m];
        for (int i = gt; i < tot; i += gs) {
            int j = i >> 7, k = i & 127;
            dst[k * outD + j] = s[i];
        }
    }
    if (gt < UCNT) {
        int t = P.tp[gt];
        atomicMax(&g_n2s[t], gt + 1);
        g_nneed[t] = 1;
    }
    gridsync();

    // ---- S1: edge scan ----
    for (int i = gt; i < NE; i += gs) {
        int s = P.src[i], d = P.dst[i];
        int su = g_n2s[s] - 1;
        if (su >= 0) {
            int j = atomicAdd(&g_deg[su], 1);
            if (j < MAXDEG) { g_eidx[su * MAXDEG + j] = i; g_nbr[su * MAXDEG + j] = d; }
            g_nneed[d] = 1;
        }
        int du = g_n2s[d] - 1;
        if (du >= 0 && d != s) {
            int j = atomicAdd(&g_deg[du], 1);
            if (j < MAXDEG) { g_eidx[du * MAXDEG + j] = i; g_nbr[du * MAXDEG + j] = s; }
            g_nneed[s] = 1;
        }
    }
    gridsync();

    // ---- S2: node compaction + per-slot sort + prefix scan (block 0) ----
    for (int i = gt; i < NN; i += gs)
        if (g_nneed[i]) { int p = atomicAdd(&g_Lcnt, 1); g_Llist[p] = i; g_nodeL[i] = p; }
    for (int u = blockIdx.x; u < UCNT; u += gridDim.x) {
        int* se = (int*)sm;
        int* sn = se + MAXDEG;
        int dg = g_deg[u]; if (dg > MAXDEG) dg = MAXDEG;
        for (int j = tid; j < dg; j += NTHR) {
            se[j] = g_eidx[u * MAXDEG + j];
            sn[j] = g_nbr[u * MAXDEG + j];
        }
        __syncthreads();
        if (tid == 0) {
            for (int i = 1; i < dg; i++) {
                int ke = se[i], kn = sn[i], j = i - 1;
                while (j >= 0 && se[j] > ke) { se[j+1] = se[j]; sn[j+1] = sn[j]; j--; }
                se[j+1] = ke; sn[j+1] = kn;
            }
        }
        __syncthreads();
        for (int j = tid; j < dg; j += NTHR) {
            g_eidx[u * MAXDEG + j] = se[j];
            g_nbr[u * MAXDEG + j] = sn[j];
        }
        __syncthreads();
    }
    if (blockIdx.x == 0) {
        if (tid < UCNT) {
            int dd = g_deg[tid];
            if (dd > MAXDEG) g_deg[tid] = MAXDEG;
        }
        __syncthreads();
        __shared__ int sCnt[UCNT];
        if (tid < UCNT) {
            int c = g_n2s[P.tp[tid]] - 1;
            int dd = g_deg[c];
            sCnt[tid] = (dd > MAXDEG) ? MAXDEG : dd;
        }
        __syncthreads();
        if (tid == 0) {
            int acc = 0;
            for (int i = 0; i < UCNT; i++) {
                g_poff[i] = acc;
                acc += sCnt[i];
            }
            g_poff[UCNT] = acc;
            g_Ptot = acc;
        }
    }
    gridsync();

    // ---- S3: per-slot finalize + metadata (thread per slot) + x-GEMM ----
    if (gt < UCNT) {
        int u = gt;
        int t = P.tp[u];
        int nl = g_nodeL[t];
        g_tgtL[u] = nl;
        int c = g_n2s[t];                 // slot+1
        g_canon[u] = c;
        int cu = c - 1;
        int dg = g_deg[cu]; if (dg > MAXDEG) dg = MAXDEG;
        g_hasnbr[u] = (dg > 0) ? 1 : 0;
        if (cu == u) g_rowSlot[nl] = u + 1;
        int off = g_poff[u];
        for (int j = 0; j < dg; j++) {
            g_pSlot[off + j] = u;
            g_pT[off + j] = P.ets[g_eidx[cu * MAXDEG + j]];
            g_pNbrRow[off + j] = g_nodeL[g_nbr[cu * MAXDEG + j]];
        }
    }
    {
        GJob j = { P.nf, 0, 0, P.in_b, g_xL, 1, c_moff[0], g_Lcnt };
        gemm_stage(sm, j);
    }
    gridsync();

    // ---- S4: tf0 + te(l0) + te(l1) ----
    {
        GJob j0 = { g_xL, 0, 0, P.ftB, g_tfL, 0, c_moff[1], g_Lcnt };
        gemm_stage(sm, j0);
        GJob j1 = { nullptr, P.teW1,       P.teB1,       P.teB2,
                    g_sTE,       4, c_moff[2], g_Ptot };
        gemm_stage(sm, j1);
        GJob j2 = { nullptr, P.teW1 + 128, P.teB1 + 128, P.teB2 + 128,
                    g_sTE + SEH, 4, c_moff[9], g_Ptot };
        gemm_stage(sm, j2);
    }
    gridsync();

    for (int l = 0; l < 2; l++) {
        int base = l * 7;
        const float* bq = P.aiB + l * 384;
        // ---- q phase ----
        {
            GJob j = { g_tfL, 0, 0, bq, g_q, 2, c_moff[3 + base], UCNT };
            gemm_stage(sm, j);
        }
        gridsync();
        // ---- kv phase (s formed on the fly) ----
        kv_stage(sm, g_sTE + (size_t)l * SEH, c_moff[4 + base], c_moff[5 + base],
                 bq + 128, bq + 256, g_Ptot);
        gridsync();
        // ---- fin phase ----
        if (l == 0) {
            for (int u = blockIdx.x; u < UCNT; u += gridDim.x)
                fin_one(sm, u, g_Wt + c_moff[6], P.aoB,
                        g_Wt + c_moff[7], P.opB,
                        g_agg + (size_t)u * HH, 0);
            gridsync();
            // ---- tf(l1) with relu(scatter) folded ----
            GJob j = { g_xL, g_agg, 0, P.ftB + 128, g_tfL, 3, c_moff[8], g_Lcnt };
            gemm_stage(sm, j);
            gridsync();
        } else {
            // ---- fin(l1) fused with pair tail: block p handles pair p ----
            float* sAgg  = sm + 2688;                 // 2 x 128
            float* sE1b  = sm + 2944;                 // 2 x 128
            float* sEmb  = sm + 3200;                 // 2 x 64
            float* sZ1   = sm + 3328;                 // 128
            float* sZ2   = sm + 3456;                 // 64
            float* sRed  = sm + 3520;                 // 2
            int nn = tid >> 7, dd = tid & 127;
            const float* o1Wt = g_Wt + c_moff[15];
            const float* o2Wt = g_Wt + c_moff[16];
            const float* l1Wt = g_Wt + c_moff[17];
            const float* l2Wt = g_Wt + c_moff[18];

            for (int p = blockIdx.x; p < 128; p += gridDim.x) {
                fin_one(sm, 2 * p,     g_Wt + c_moff[13], P.aoB + 128,
                        g_Wt + c_moff[14], P.opB + 128, sAgg, 1);
                fin_one(sm, 2 * p + 1, g_Wt + c_moff[13], P.aoB + 128,
                        g_Wt + c_moff[14], P.opB + 128, sAgg + 128, 1);
                // tail
                sE1b[nn * 128 + dd] =
                    fmaxf(matvec(sAgg + nn * 128, o1Wt, dd, HH, HH) + P.o1B[dd], 0.f);
                __syncthreads();
                if (dd < 64)
                    sEmb[nn * 64 + dd] =
                        matvec(sE1b + nn * 128, o2Wt, dd, 64, HH) + P.o2B[dd];
                __syncthreads();
                if (tid < 128) {
                    float a0 = 0.f, a1 = 0.f;
#pragma unroll 8
                    for (int k = 0; k < 64; k += 2) {
                        a0 = fmaf(sEmb[k],     l1Wt[(k)      * HH + dd], a0);
                        a1 = fmaf(sEmb[k + 1], l1Wt[(k + 1)  * HH + dd], a1);
                    }
#pragma unroll 8
                    for (int k = 0; k < 64; k += 2) {
                        a0 = fmaf(sEmb[64 + k],     l1Wt[(64 + k)     * HH + dd], a0);
                        a1 = fmaf(sEmb[64 + k + 1], l1Wt[(64 + k + 1) * HH + dd], a1);
                    }
                    sZ1[dd] = fmaxf(a0 + a1 + P.l1B[dd], 0.f);
                }
                __syncthreads();
                if (tid < 64)
                    sZ2[tid] = fmaxf(matvec(sZ1, l2Wt, tid, 64, HH) + P.l2B[tid], 0.f);
                __syncthreads();
                if (tid < 64) {
                    float part = sZ2[tid] * P.l3W[tid];
                    part += __shfl_xor_sync(0xffffffffu, part, 16);
                    part += __shfl_xor_sync(0xffffffffu, part, 8);
                    part += __shfl_xor_sync(0xffffffffu, part, 4);
                    part += __shfl_xor_sync(0xffffffffu, part, 2);
                    part += __shfl_xor_sync(0xffffffffu, part, 1);
                    if ((tid & 31) == 0) sRed[tid >> 5] = part;
                }
                __syncthreads();
                if (tid == 0)
                    out[p] = 1.f / (1.f + expf(-(sRed[0] + sRed[1] + P.l3B[0])));
                __syncthreads();
            }
        }
    }

    // ---- cleanup for next graph replay (no barrier needed: disjoint state) ----
    for (int i = gt; i < NN; i += gs) g_nneed[i] = 0;
    if (gt < UCNT) {
        g_n2s[P.tp[gt]] = 0;
        g_deg[gt] = 0;
        g_rowSlot[g_tgtL[gt]] = 0;
    }
    if (gt == 0) g_Lcnt = 0;
}

// ---------------- launch ----------------
extern "C" void kernel_launch(void* const* d_in, const int* in_sizes, int n_in,
                              void* d_out, int out_size) {
    const float* nf   = (const float*)d_in[0];
    const int*   eidx = (const int*)d_in[1];
    const float* ets  = (const float*)d_in[2];
    const int*   tp   = (const int*)d_in[3];
    const float* in_W = (const float*)d_in[4];
    const float* in_b = (const float*)d_in[5];
    const float* teW1 = (const float*)d_in[6];
    const float* teB1 = (const float*)d_in[7];
    const float* teW2 = (const float*)d_in[8];
    const float* teB2 = (const float*)d_in[9];
    const float* aiW  = (const float*)d_in[10];
    const float* aiB  = (const float*)d_in[11];
    const float* aoW  = (const float*)d_in[12];
    const float* aoB  = (const float*)d_in[13];
    const float* ftW  = (const float*)d_in[14];
    const float* ftB  = (const float*)d_in[15];
    const float* opW  = (const float*)d_in[16];
    const float* opB  = (const float*)d_in[17];
    const float* o1W  = (const float*)d_in[18];
    const float* o1B  = (const float*)d_in[19];
    const float* o2W  = (const float*)d_in[20];
    const float* o2B  = (const float*)d_in[21];
    const float* l1W  = (const float*)d_in[22];
    const float* l1B  = (const float*)d_in[23];
    const float* l2W  = (const float*)d_in[24];
    const float* l2B  = (const float*)d_in[25];
    const float* l3W  = (const float*)d_in[26];
    const float* l3B  = (const float*)d_in[27];
    float* out = (float*)d_out;

    Params P;
    P.wsrc[0] = in_W;
    for (int l = 0; l < 2; l++) {
        P.wsrc[1 + 7*l] = ftW + l * 16384;
        P.wsrc[2 + 7*l] = teW2 + l * 16384;
        P.wsrc[3 + 7*l] = aiW + l * 384 * 128;            // Wq
        P.wsrc[4 + 7*l] = aiW + l * 384 * 128 + 16384;    // Wk
        P.wsrc[5 + 7*l] = aiW + l * 384 * 128 + 32768;    // Wv
        P.wsrc[6 + 7*l] = aoW + l * 16384;
        P.wsrc[7 + 7*l] = opW + l * 16384;
    }
    P.wsrc[15] = o1W; P.wsrc[16] = o2W; P.wsrc[17] = l1W; P.wsrc[18] = l2W;
    P.tp = tp; P.src = eidx; P.dst = eidx + NE;
    P.ets = ets; P.nf = nf;
    P.in_b = in_b; P.teW1 = teW1; P.teB1 = teB1; P.teB2 = teB2;
    P.aiB = aiB; P.aoB = aoB; P.ftB = ftB; P.opB = opB;
    P.o1B = o1B; P.o2B = o2B; P.l1B = l1B; P.l2B = l2B;
    P.l3W = l3W; P.l3B = l3B;

    cudaFuncSetAttribute(k_mega, cudaFuncAttributeMaxDynamicSharedMemorySize, SMEM_SZ);

    int nSM = 148;
    cudaDeviceGetAttribute(&nSM, cudaDevAttrMultiProcessorCount, 0);
    int nb = nSM;              // 1 block per SM
    if (nb < 8) nb = 8;

    k_mega<<<nb, NTHR, SMEM_SZ>>>(P, out);
}

// round 14
// speedup vs baseline: 1.0706x; 1.0706x over previous
#include <cuda_runtime.h>
#include <math.h>

#define NN 20000
#define NE 50000
#define HH 128
#define UCNT 256
#define MAXDEG 512
#define DSCALE 0.17677669529663687f   // 1/sqrt(32)
#define NTHR 256
#define SMEM_SZ 167936                // 2x64KB weights + 4KB rows + 32KB partials

// ---------------- device scratch (static, no allocation) ----------------
__device__ int   g_n2s[NN];          // slot+1; 0 = none
__device__ unsigned char g_nneed[NN];
__device__ int   g_deg[UCNT];
__device__ int   g_eidx[UCNT * MAXDEG];
__device__ int   g_nbr[UCNT * MAXDEG];
__device__ int   g_Lcnt;
__device__ int   g_Llist[NN], g_nodeL[NN];
__device__ int   g_tgtL[UCNT], g_canon[UCNT], g_hasnbr[UCNT];
__device__ int   g_rowSlot[NN];      // slot+1; 0 = none

__device__ int   g_poff[UCNT + 1];
__device__ int   g_Ptot;
__device__ int   g_pSlot[UCNT * MAXDEG];
__device__ float g_pT[UCNT * MAXDEG];
__device__ int   g_pNbrRow[UCNT * MAXDEG];

__device__ float g_xL[NN * HH];
__device__ float g_tfL[NN * HH];
__device__ float g_q[UCNT * HH];
__device__ float g_agg[UCNT * HH];
__device__ float g_s[(size_t)UCNT * MAXDEG * HH];
__device__ float g_V[(size_t)UCNT * MAXDEG * HH];
__device__ float g_sc[UCNT * MAXDEG * 4];

// base weights (19 transposed mats) + 2 combined (Wop@Wao) mats
#define WT_TOTAL 327680
#define CW0 294912
#define CW1 311296
__device__ float g_Wt[WT_TOTAL];
__device__ float g_cb[2 * HH];       // combined biases Wop@aoB + opB

__constant__ int c_moutD[19] = {128,128,128,128,128,128,128,128,128,
                                128,128,128,128,128,128,128, 64,128, 64};
__constant__ int c_moff[19]  = {0,16384,32768,49152,65536,81920,98304,114688,
                                131072,147456,163840,180224,196608,212992,
                                229376,245760,262144,270336,286720};

// ---------------- device-wide barrier ----------------
__device__ unsigned g_cnt8[8];
__device__ unsigned g_rootc;
__device__ volatile unsigned g_ep;

__device__ __forceinline__ void gridsync() {
    __syncthreads();
    if (threadIdx.x == 0) {
        unsigned nb = gridDim.x;
        unsigned e = g_ep;
        __threadfence();
        unsigned g = blockIdx.x & 7u;
        unsigned sz = nb / 8u + ((g < (nb & 7u)) ? 1u : 0u);
        if (atomicAdd(&g_cnt8[g], 1u) == sz - 1u) {
            g_cnt8[g] = 0u;
            __threadfence();
            if (atomicAdd(&g_rootc, 1u) == 7u) {
                g_rootc = 0u;
                __threadfence();
                g_ep = e + 1u;
            }
        }
        while (g_ep == e) { }
        __threadfence();
    }
    __syncthreads();
}

// ---------------- helpers ----------------
__device__ __forceinline__ float4 relu4(float4 v) {
    v.x = fmaxf(v.x, 0.f); v.y = fmaxf(v.y, 0.f);
    v.z = fmaxf(v.z, 0.f); v.w = fmaxf(v.w, 0.f);
    return v;
}

__device__ __forceinline__ float matvec64(const float* __restrict__ v,
                                          const float* __restrict__ Wt,
                                          int d, int stride) {
    float a0 = 0.f, a1 = 0.f, a2 = 0.f, a3 = 0.f;
#pragma unroll 8
    for (int k = 0; k < 64; k += 4) {
        a0 = fmaf(v[k],     Wt[(k)     * stride + d], a0);
        a1 = fmaf(v[k + 1], Wt[(k + 1) * stride + d], a1);
        a2 = fmaf(v[k + 2], Wt[(k + 2) * stride + d], a2);
        a3 = fmaf(v[k + 3], Wt[(k + 3) * stride + d], a3);
    }
    return (a0 + a1) + (a2 + a3);
}

__device__ __forceinline__ float matvec(const float* __restrict__ v,
                                        const float* __restrict__ Wt,
                                        int d, int stride, int K) {
    float a0 = 0.f, a1 = 0.f, a2 = 0.f, a3 = 0.f;
#pragma unroll 8
    for (int k = 0; k < K; k += 4) {
        a0 = fmaf(v[k],     Wt[(k)     * stride + d], a0);
        a1 = fmaf(v[k + 1], Wt[(k + 1) * stride + d], a1);
        a2 = fmaf(v[k + 2], Wt[(k + 2) * stride + d], a2);
        a3 = fmaf(v[k + 3], Wt[(k + 3) * stride + d], a3);
    }
    return (a0 + a1) + (a2 + a3);
}

// ---------------- 8-row k-split GEMM stage (smem weights) -------------------
// gsel: 0 linear, 1 Llist, 2 tgtL, 3 relu(rowSlot? aggAux : in), 4 time-encode
// mode: 0 plain(+bias), 1 +bias+tf[nbrRow]
struct GJob {
    const float* in; const float* pA; const float* pB; const float* bias;
    float* out;
    int gsel, mode, woff, cnt;
};

__device__ void gemm_stage(float* sm, GJob jb) {
    float* s_w = sm;                                        // 16384 floats (64KB)
    float (*s_in)[HH] = (float(*)[HH])(sm + 16384);         // 8 x 128
    float4 (*s_part)[8][32] = (float4(*)[8][32])(sm + 16384 + 8 * HH);
    int tid = threadIdx.x, w = tid >> 5, lane = tid & 31;
    int k4 = lane * 4;
    int cnt = jb.cnt;
    int T = (cnt + 7) >> 3;
    const float4* wp = (const float4*)(g_Wt + jb.woff);
    bool loaded = false;

    for (int t = blockIdx.x; t < T; t += gridDim.x) {
        if (!loaded) {
            for (int i = tid; i < 4096; i += NTHR)
                ((float4*)s_w)[i] = wp[i];
            loaded = true;
        }
        int r0 = t * 8;
        {
            int r = r0 + w;
            int rc = (r < cnt) ? r : (cnt - 1);
            float4 v;
            if (jb.gsel == 0) {
                v = *(const float4*)(jb.in + (size_t)rc * HH + k4);
            } else if (jb.gsel == 1) {
                v = *(const float4*)(jb.in + (size_t)g_Llist[rc] * HH + k4);
            } else if (jb.gsel == 2) {
                v = *(const float4*)(jb.in + (size_t)g_tgtL[rc] * HH + k4);
            } else if (jb.gsel == 3) {
                int s = g_rowSlot[rc];
                const float* src = (s > 0) ? (jb.pA + (size_t)(s - 1) * HH)
                                           : (jb.in + (size_t)rc * HH);
                v = relu4(*(const float4*)(src + k4));
            } else {  // 4: time-encode stage 1
                float tv = g_pT[rc];
                float4 w1 = *(const float4*)(jb.pA + k4);
                float4 b1 = *(const float4*)(jb.pB + k4);
                v.x = fmaxf(fmaf(tv, w1.x, b1.x), 0.f);
                v.y = fmaxf(fmaf(tv, w1.y, b1.y), 0.f);
                v.z = fmaxf(fmaf(tv, w1.z, b1.z), 0.f);
                v.w = fmaxf(fmaf(tv, w1.w, b1.w), 0.f);
            }
            *(float4*)(&s_in[w][k4]) = v;
        }
        __syncthreads();

        float4 acc[8];
#pragma unroll
        for (int r = 0; r < 8; r++) acc[r] = make_float4(0.f, 0.f, 0.f, 0.f);
        int kbase = w * 16;
#pragma unroll
        for (int kk = 0; kk < 16; kk++) {
            int k = kbase + kk;
            float4 wv = ((const float4*)s_w)[k * 32 + lane];
#pragma unroll
            for (int r = 0; r < 8; r++) {
                float xv = s_in[r][k];
                acc[r].x = fmaf(xv, wv.x, acc[r].x);
                acc[r].y = fmaf(xv, wv.y, acc[r].y);
                acc[r].z = fmaf(xv, wv.z, acc[r].z);
                acc[r].w = fmaf(xv, wv.w, acc[r].w);
            }
        }
#pragma unroll
        for (int r = 0; r < 8; r++) s_part[w][r][lane] = acc[r];
        __syncthreads();

        {
            float4 o = s_part[0][w][lane];
#pragma unroll
            for (int ww = 1; ww < 8; ww++) {
                float4 p = s_part[ww][w][lane];
                o.x += p.x; o.y += p.y; o.z += p.z; o.w += p.w;
            }
            float4 bv = jb.bias ? ((const float4*)jb.bias)[lane]
                                : make_float4(0.f, 0.f, 0.f, 0.f);
            int row = r0 + w;
            if (row < cnt) {
                o.x += bv.x; o.y += bv.y; o.z += bv.z; o.w += bv.w;
                if (jb.mode == 1) {
                    int nr = g_pNbrRow[row];
                    float4 tv = *(const float4*)(g_tfL + (size_t)nr * HH + k4);
                    o.x += tv.x; o.y += tv.y; o.z += tv.z; o.w += tv.w;
                }
                *(float4*)(jb.out + (size_t)row * HH + k4) = o;
            }
        }
        __syncthreads();
    }
}

// ---------------- fused K-score + V stage (both weights in smem) ------------
__device__ void kv_stage(float* sm, int wkoff, int wvoff,
                         const float* __restrict__ bk,
                         const float* __restrict__ bvv, int cnt) {
    float* s_wk = sm;
    float* s_wv = sm + 16384;
    float (*s_in)[HH] = (float(*)[HH])(sm + 32768);
    float4 (*s_part)[8][32] = (float4(*)[8][32])(sm + 32768 + 8 * HH);
    int tid = threadIdx.x, w = tid >> 5, lane = tid & 31;
    int k4 = lane * 4;
    int T = (cnt + 7) >> 3;
    const float4* wkp = (const float4*)(g_Wt + wkoff);
    const float4* wvp = (const float4*)(g_Wt + wvoff);
    bool loaded = false;

    for (int t = blockIdx.x; t < T; t += gridDim.x) {
        if (!loaded) {
            for (int i = tid; i < 4096; i += NTHR) {
                ((float4*)s_wk)[i] = wkp[i];
                ((float4*)s_wv)[i] = wvp[i];
            }
            loaded = true;
        }
        int r0 = t * 8;
        {
            int r = r0 + w;
            int rc = (r < cnt) ? r : (cnt - 1);
            *(float4*)(&s_in[w][k4]) =
                *(const float4*)(g_s + (size_t)rc * HH + k4);
        }
        __syncthreads();

        int kbase = w * 16;
        // ---- K + score epilogue ----
        {
            float4 acc[8];
#pragma unroll
            for (int r = 0; r < 8; r++) acc[r] = make_float4(0.f, 0.f, 0.f, 0.f);
#pragma unroll
            for (int kk = 0; kk < 16; kk++) {
                int k = kbase + kk;
                float4 wv = ((const float4*)s_wk)[k * 32 + lane];
#pragma unroll
                for (int r = 0; r < 8; r++) {
                    float xv = s_in[r][k];
                    acc[r].x = fmaf(xv, wv.x, acc[r].x);
                    acc[r].y = fmaf(xv, wv.y, acc[r].y);
                    acc[r].z = fmaf(xv, wv.z, acc[r].z);
                    acc[r].w = fmaf(xv, wv.w, acc[r].w);
                }
            }
#pragma unroll
            for (int r = 0; r < 8; r++) s_part[w][r][lane] = acc[r];
        }
        __syncthreads();
        {
            float4 o = s_part[0][w][lane];
#pragma unroll
            for (int ww = 1; ww < 8; ww++) {
                float4 p = s_part[ww][w][lane];
                o.x += p.x; o.y += p.y; o.z += p.z; o.w += p.w;
            }
            float4 bv = ((const float4*)bk)[lane];
            int row = r0 + w;
            int rowc = (row < cnt) ? row : (cnt - 1);
            int u = g_pSlot[rowc];
            float4 q4 = *(const float4*)(g_q + (size_t)u * HH + k4);
            float p = (o.x + bv.x) * q4.x + (o.y + bv.y) * q4.y
                    + (o.z + bv.z) * q4.z + (o.w + bv.w) * q4.w;
            p += __shfl_xor_sync(0xffffffffu, p, 4);
            p += __shfl_xor_sync(0xffffffffu, p, 2);
            p += __shfl_xor_sync(0xffffffffu, p, 1);
            if ((lane & 7) == 0 && row < cnt)
                g_sc[rowc * 4 + (lane >> 3)] = p * DSCALE;
        }
        __syncthreads();
        // ---- V ----
        {
            float4 acc[8];
#pragma unroll
            for (int r = 0; r < 8; r++) acc[r] = make_float4(0.f, 0.f, 0.f, 0.f);
#pragma unroll
            for (int kk = 0; kk < 16; kk++) {
                int k = kbase + kk;
                float4 wv = ((const float4*)s_wv)[k * 32 + lane];
#pragma unroll
                for (int r = 0; r < 8; r++) {
                    float xv = s_in[r][k];
                    acc[r].x = fmaf(xv, wv.x, acc[r].x);
                    acc[r].y = fmaf(xv, wv.y, acc[r].y);
                    acc[r].z = fmaf(xv, wv.z, acc[r].z);
                    acc[r].w = fmaf(xv, wv.w, acc[r].w);
                }
            }
#pragma unroll
            for (int r = 0; r < 8; r++) s_part[w][r][lane] = acc[r];
        }
        __syncthreads();
        {
            float4 o = s_part[0][w][lane];
#pragma unroll
            for (int ww = 1; ww < 8; ww++) {
                float4 p = s_part[ww][w][lane];
                o.x += p.x; o.y += p.y; o.z += p.z; o.w += p.w;
            }
            float4 bv = ((const float4*)bvv)[lane];
            int row = r0 + w;
            if (row < cnt) {
                o.x += bv.x; o.y += bv.y; o.z += bv.z; o.w += bv.w;
                *(float4*)(g_V + (size_t)row * HH + k4) = o;
            }
        }
        __syncthreads();
    }
}

// ---------------- per-slot finish (combined attn_out+op matvec) -------------
__device__ void fin_stage(float* sm,
                          const float* __restrict__ Wc,  const float* __restrict__ cb,
                          const float* __restrict__ Wop, const float* __restrict__ opB) {
    float* sSc  = sm;                  // MAXDEG*4
    float* sO   = sm + MAXDEG * 4;     // 128
    float* sTgt = sO + 128;            // 128
    float (*sPart)[128] = (float(*)[128])(sTgt + 128);   // 2 x 128
    int tid = threadIdx.x;
    int half = tid >> 7;
    int dd = tid & 127;
    int hh2 = dd >> 5;

    for (int u = blockIdx.x; u < UCNT; u += gridDim.x) {
        int off = g_poff[u];
        int dg = g_poff[u + 1] - off;
        for (int i = tid; i < dg * 4; i += NTHR) sSc[i] = g_sc[off * 4 + i];
        if (tid < 128) sTgt[dd] = g_tfL[(size_t)g_tgtL[u] * HH + dd];
        __syncthreads();

        if (tid < 128) {
            int lane = tid & 31, hh = tid >> 5;
            float mx = -1e30f;
            for (int j = lane; j < dg; j += 32) mx = fmaxf(mx, sSc[j * 4 + hh]);
#pragma unroll
            for (int m = 16; m > 0; m >>= 1)
                mx = fmaxf(mx, __shfl_xor_sync(0xffffffffu, mx, m));
            float smv = 0.f;
            for (int j = lane; j < dg; j += 32) {
                float p = expf(sSc[j * 4 + hh] - mx);
                sSc[j * 4 + hh] = p;
                smv += p;
            }
#pragma unroll
            for (int m = 16; m > 0; m >>= 1)
                smv += __shfl_xor_sync(0xffffffffu, smv, m);
            float inv = (dg > 0) ? (1.f / smv) : 0.f;
            for (int j = lane; j < dg; j += 32) sSc[j * 4 + hh] *= inv;
        }
        __syncthreads();

        {
            float p = 0.f;
            for (int j = half; j < dg; j += 2)
                p = fmaf(sSc[j * 4 + hh2], g_V[((size_t)(off + j)) * HH + dd], p);
            sPart[half][dd] = p;
        }
        __syncthreads();
        if (tid < 128) sO[dd] = sPart[0][dd] + sPart[1][dd];
        __syncthreads();

        // single combined matvec: (Wop@Wao)·o + cb  OR  Wop·tf[tgt] + opB
        {
            const float* src = (dg > 0) ? sO : sTgt;
            const float* W   = (dg > 0) ? Wc : Wop;
            sPart[half][dd] = matvec64(src + half * 64, W + half * 64 * HH, dd, HH);
        }
        __syncthreads();
        if (tid < 128) {
            const float* bb = (dg > 0) ? cb : opB;
            g_agg[(size_t)u * HH + dd] = sPart[0][dd] + sPart[1][dd] + bb[dd];
        }
        __syncthreads();
    }
}

// ---------------- mega kernel ----------------
struct Params {
    const float* wsrc[19];
    const int *tp, *src, *dst;
    const float *ets, *nf;
    const float *in_b, *teW1, *teB1, *teB2, *aiB, *aoB, *ftB, *opB;
    const float *o1B, *o2B, *l1B, *l2B, *l3W, *l3B;
};

__global__ void __launch_bounds__(NTHR)
k_mega(Params P, float* out) {
    extern __shared__ float sm[];
    const int gt = blockIdx.x * NTHR + threadIdx.x;
    const int gs = gridDim.x * NTHR;
    int tid = threadIdx.x;

    // ---- S0: weight transpose + mark targets ----
    for (int m = 0; m < 19; m++) {
        int outD = c_moutD[m];
        int tot = outD * 128;
        const float* s = P.wsrc[m];
        float* dst = g_Wt + c_moff[m];
        for (int i = gt; i < tot; i += gs) {
            int j = i >> 7, k = i & 127;
            dst[k * outD + j] = s[i];
        }
    }
    if (gt < UCNT) {
        int t = P.tp[gt];
        atomicMax(&g_n2s[t], gt + 1);
        g_nneed[t] = 1;
    }
    gridsync();

    // ---- S1: edge scan ----
    for (int i = gt; i < NE; i += gs) {
        int s = P.src[i], d = P.dst[i];
        int su = g_n2s[s] - 1;
        if (su >= 0) {
            int j = atomicAdd(&g_deg[su], 1);
            if (j < MAXDEG) { g_eidx[su * MAXDEG + j] = i; g_nbr[su * MAXDEG + j] = d; }
            g_nneed[d] = 1;
        }
        int du = g_n2s[d] - 1;
        if (du >= 0 && d != s) {
            int j = atomicAdd(&g_deg[du], 1);
            if (j < MAXDEG) { g_eidx[du * MAXDEG + j] = i; g_nbr[du * MAXDEG + j] = s; }
            g_nneed[s] = 1;
        }
    }
    gridsync();

    // ---- S2: node compaction + deg clamp + pair prefix scan (block 0) ----
    for (int i = gt; i < NN; i += gs)
        if (g_nneed[i]) { int p = atomicAdd(&g_Lcnt, 1); g_Llist[p] = i; g_nodeL[i] = p; }
    if (blockIdx.x == 0) {
        if (tid < UCNT) {
            int dd = g_deg[tid];
            if (dd > MAXDEG) g_deg[tid] = MAXDEG;
        }
        __syncthreads();
        __shared__ int sCnt[UCNT];
        if (tid < UCNT) {
            int c = g_n2s[P.tp[tid]] - 1;
            sCnt[tid] = g_deg[c];
        }
        __syncthreads();
        if (tid == 0) {
            int acc = 0;
            for (int i = 0; i < UCNT; i++) {
                g_poff[i] = acc;
                acc += sCnt[i];
            }
            g_poff[UCNT] = acc;
            g_Ptot = acc;
        }
    }
    gridsync();

    // ---- S3: per-slot sort + finalize + pSlot fill, then x-GEMM + combines ----
    for (int u = blockIdx.x; u < UCNT; u += gridDim.x) {
        int* se = (int*)sm;
        int* sn = se + MAXDEG;
        int dg = g_deg[u];
        for (int j = tid; j < dg; j += NTHR) {
            se[j] = g_eidx[u * MAXDEG + j];
            sn[j] = g_nbr[u * MAXDEG + j];
        }
        __syncthreads();
        if (tid == 0) {
            for (int i = 1; i < dg; i++) {
                int ke = se[i], kn = sn[i], j = i - 1;
                while (j >= 0 && se[j] > ke) { se[j+1] = se[j]; sn[j+1] = sn[j]; j--; }
                se[j+1] = ke; sn[j+1] = kn;
            }
            int t = P.tp[u];
            g_tgtL[u] = g_nodeL[t];
            int c = g_n2s[t];            // slot+1
            g_canon[u] = c;
            g_hasnbr[u] = (g_deg[c - 1] > 0) ? 1 : 0;
            if (c - 1 == u) g_rowSlot[g_nodeL[t]] = u + 1;
        }
        __syncthreads();
        for (int j = tid; j < dg; j += NTHR) {
            g_eidx[u * MAXDEG + j] = se[j];
            g_nbr[u * MAXDEG + j] = sn[j];
        }
        int off = g_poff[u], cntp = g_poff[u + 1] - off;
        for (int j = tid; j < cntp; j += NTHR) g_pSlot[off + j] = u;
        __syncthreads();
    }
    {
        GJob j = { P.nf, 0, 0, P.in_b, g_xL, 1, 0, c_moff[0], g_Lcnt };
        gemm_stage(sm, j);
        // combined Wop@Wao matrices (rows = Wao_t rows, weights = Wop_t)
        GJob c0 = { g_Wt + c_moff[6],  0, 0, nullptr, g_Wt + CW0, 0, 0, c_moff[7],  128 };
        gemm_stage(sm, c0);
        GJob c1 = { g_Wt + c_moff[13], 0, 0, nullptr, g_Wt + CW1, 0, 0, c_moff[14], 128 };
        gemm_stage(sm, c1);
    }
    // combined biases: cb = Wop_t^T aoB + opB
    if (gt < 2 * HH) {
        int l = gt >> 7, d = gt & 127;
        const float* Wop_t = g_Wt + c_moff[7 + 7 * l];
        const float* aoB = P.aoB + l * HH;
        float a = P.opB[l * HH + d];
        for (int k = 0; k < HH; k++)
            a = fmaf(aoB[k], Wop_t[k * HH + d], a);
        g_cb[gt] = a;
    }
    gridsync();

    // ---- S4: pair metadata fill + tf(l0) ----
    {
        int Pt = g_Ptot;
        for (int p = gt; p < Pt; p += gs) {
            int u = g_pSlot[p];
            int cu = g_canon[u] - 1;
            int j = p - g_poff[u];
            g_pT[p] = P.ets[g_eidx[cu * MAXDEG + j]];
            g_pNbrRow[p] = g_nodeL[g_nbr[cu * MAXDEG + j]];
        }
        GJob j = { g_xL, 0, 0, P.ftB, g_tfL, 0, 0, c_moff[1], g_Lcnt };
        gemm_stage(sm, j);
    }
    gridsync();

    for (int l = 0; l < 2; l++) {
        int base = l * 7;
        const float* bq = P.aiB + l * 384;
        // ---- E1: s = tf[nbr] + te(t)@W2t + b2 ; q = tf[tgt]@Wqt + bq ----
        {
            GJob j1 = { nullptr, P.teW1 + l*128, P.teB1 + l*128, P.teB2 + l*128,
                        g_s, 4, 1, c_moff[2 + base], g_Ptot };
            gemm_stage(sm, j1);
            GJob j2 = { g_tfL, 0, 0, bq, g_q, 2, 0, c_moff[3 + base], UCNT };
            gemm_stage(sm, j2);
        }
        gridsync();
        // ---- E2 fused: scores + V in one pass over g_s ----
        kv_stage(sm, c_moff[4 + base], c_moff[5 + base],
                 bq + 128, bq + 256, g_Ptot);
        gridsync();
        // ---- fin: softmax + weighted V + combined (attn_out∘op) ----
        fin_stage(sm, g_Wt + (l == 0 ? CW0 : CW1), g_cb + l * HH,
                  g_Wt + c_moff[7 + base], P.opB + l * HH);
        gridsync();
        // ---- tf(l1) with relu(scatter) folded ----
        if (l == 0) {
            GJob j = { g_xL, g_agg, 0, P.ftB + 128, g_tfL, 3, 0, c_moff[8], g_Lcnt };
            gemm_stage(sm, j);
            gridsync();
        }
    }

    // ---- tail: fused out1/out2/lp1/lp2/lp3 per pair ----
    {
        float (*sAgg)[HH] = (float(*)[HH])sm;
        float (*sE1)[HH]  = (float(*)[HH])(sm + 256);
        float (*sEmb)[64] = (float(*)[64])(sm + 512);
        float* sZ1 = sm + 640;
        float* sZ2 = sm + 768;
        float* sRed = sm + 832;
        int nn = tid >> 7, dd = tid & 127;
        const float* o1Wt = g_Wt + c_moff[15];
        const float* o2Wt = g_Wt + c_moff[16];
        const float* l1Wt = g_Wt + c_moff[17];
        const float* l2Wt = g_Wt + c_moff[18];

        for (int p = blockIdx.x; p < 128; p += gridDim.x) {
            sAgg[nn][dd] = fmaxf(g_agg[(size_t)(2 * p + nn) * HH + dd], 0.f);
            __syncthreads();
            sE1[nn][dd] = fmaxf(matvec(sAgg[nn], o1Wt, dd, HH, HH) + P.o1B[dd], 0.f);
            __syncthreads();
            if (dd < 64)
                sEmb[nn][dd] = matvec(sE1[nn], o2Wt, dd, 64, HH) + P.o2B[dd];
            __syncthreads();
            if (tid < 128) {
                float a0 = 0.f, a1 = 0.f;
#pragma unroll 8
                for (int k = 0; k < 64; k += 2) {
                    a0 = fmaf(sEmb[0][k],     l1Wt[(k)      * HH + dd], a0);
                    a1 = fmaf(sEmb[0][k + 1], l1Wt[(k + 1)  * HH + dd], a1);
                }
#pragma unroll 8
                for (int k = 0; k < 64; k += 2) {
                    a0 = fmaf(sEmb[1][k],     l1Wt[(64 + k)     * HH + dd], a0);
                    a1 = fmaf(sEmb[1][k + 1], l1Wt[(64 + k + 1) * HH + dd], a1);
                }
                sZ1[dd] = fmaxf(a0 + a1 + P.l1B[dd], 0.f);
            }
            __syncthreads();
            if (tid < 64)
                sZ2[tid] = fmaxf(matvec(sZ1, l2Wt, tid, 64, HH) + P.l2B[tid], 0.f);
            __syncthreads();
            if (tid < 64) {
                float part = sZ2[tid] * P.l3W[tid];
                part += __shfl_xor_sync(0xffffffffu, part, 16);
                part += __shfl_xor_sync(0xffffffffu, part, 8);
                part += __shfl_xor_sync(0xffffffffu, part, 4);
                part += __shfl_xor_sync(0xffffffffu, part, 2);
                part += __shfl_xor_sync(0xffffffffu, part, 1);
                if ((tid & 31) == 0) sRed[tid >> 5] = part;
            }
            __syncthreads();
            if (tid == 0)
                out[p] = 1.f / (1.f + expf(-(sRed[0] + sRed[1] + P.l3B[0])));
            __syncthreads();
        }
    }

    // ---- cleanup for next graph replay ----
    for (int i = gt; i < NN; i += gs) g_nneed[i] = 0;
    if (gt < UCNT) {
        g_n2s[P.tp[gt]] = 0;
        g_deg[gt] = 0;
        g_rowSlot[g_tgtL[gt]] = 0;
    }
    if (gt == 0) g_Lcnt = 0;
}

// ---------------- launch ----------------
extern "C" void kernel_launch(void* const* d_in, const int* in_sizes, int n_in,
                              void* d_out, int out_size) {
    const float* nf   = (const float*)d_in[0];
    const int*   eidx = (const int*)d_in[1];
    const float* ets  = (const float*)d_in[2];
    const int*   tp   = (const int*)d_in[3];
    const float* in_W = (const float*)d_in[4];
    const float* in_b = (const float*)d_in[5];
    const float* teW1 = (const float*)d_in[6];
    const float* teB1 = (const float*)d_in[7];
    const float* teW2 = (const float*)d_in[8];
    const float* teB2 = (const float*)d_in[9];
    const float* aiW  = (const float*)d_in[10];
    const float* aiB  = (const float*)d_in[11];
    const float* aoW  = (const float*)d_in[12];
    const float* aoB  = (const float*)d_in[13];
    const float* ftW  = (const float*)d_in[14];
    const float* ftB  = (const float*)d_in[15];
    const float* opW  = (const float*)d_in[16];
    const float* opB  = (const float*)d_in[17];
    const float* o1W  = (const float*)d_in[18];
    const float* o1B  = (const float*)d_in[19];
    const float* o2W  = (const float*)d_in[20];
    const float* o2B  = (const float*)d_in[21];
    const float* l1W  = (const float*)d_in[22];
    const float* l1B  = (const float*)d_in[23];
    const float* l2W  = (const float*)d_in[24];
    const float* l2B  = (const float*)d_in[25];
    const float* l3W  = (const float*)d_in[26];
    const float* l3B  = (const float*)d_in[27];
    float* out = (float*)d_out;

    Params P;
    P.wsrc[0] = in_W;
    for (int l = 0; l < 2; l++) {
        P.wsrc[1 + 7*l] = ftW + l * 16384;
        P.wsrc[2 + 7*l] = teW2 + l * 16384;
        P.wsrc[3 + 7*l] = aiW + l * 384 * 128;            // Wq
        P.wsrc[4 + 7*l] = aiW + l * 384 * 128 + 16384;    // Wk
        P.wsrc[5 + 7*l] = aiW + l * 384 * 128 + 32768;    // Wv
        P.wsrc[6 + 7*l] = aoW + l * 16384;
        P.wsrc[7 + 7*l] = opW + l * 16384;
    }
    P.wsrc[15] = o1W; P.wsrc[16] = o2W; P.wsrc[17] = l1W; P.wsrc[18] = l2W;
    P.tp = tp; P.src = eidx; P.dst = eidx + NE;
    P.ets = ets; P.nf = nf;
    P.in_b = in_b; P.teW1 = teW1; P.teB1 = teB1; P.teB2 = teB2;
    P.aiB = aiB; P.aoB = aoB; P.ftB = ftB; P.opB = opB;
    P.o1B = o1B; P.o2B = o2B; P.l1B = l1B; P.l2B = l2B;
    P.l3W = l3W; P.l3B = l3B;

    cudaFuncSetAttribute(k_mega, cudaFuncAttributeMaxDynamicSharedMemorySize, SMEM_SZ);

    int nSM = 148;
    cudaDeviceGetAttribute(&nSM, cudaDevAttrMultiProcessorCount, 0);
    int nb = nSM;              // 1 block per SM
    if (nb < 8) nb = 8;

    k_mega<<<nb, NTHR, SMEM_SZ>>>(P, out);
}